// round 9
// baseline (speedup 1.0000x reference)
#include <cuda_runtime.h>
#include <stdint.h>

// Problem constants (fixed by setup_inputs)
#define B_SZ     32
#define C_SZ     384
#define T_SZ     1024
#define MAXLEN   8192
#define CH_OUT   (C_SZ + 2)          // 386
#define MAX_DUR  10000

#define THREADS     256
#define POS_PER_TH  2
#define POS_CHUNK   (THREADS * POS_PER_TH)   // 512
#define N_PCHUNK    (MAXLEN / POS_CHUNK)     // 16
#define CH_GRP      8
#define N_YGRP      (C_SZ / CH_GRP + 1)      // 48 full groups + 1 extras group

// Scratch (allocation-free rule: device globals)
__device__ int g_ends[B_SZ][T_SZ];   // inclusive cumsum of clipped durations
__device__ int g_dval[B_SZ][T_SZ];   // clipped durations
__device__ int g_tok [B_SZ][MAXLEN]; // token per output position, -1 = invalid (monotone tail)

// ---------------------------------------------------------------------------
// Kernel 1: per-batch scan + token-map scatter + tail fill + mel_len.
// One block per batch, 1024 threads. Warp-shfl scan (2 block syncs).
// ---------------------------------------------------------------------------
__global__ __launch_bounds__(1024) void prep_kernel(
    const int* __restrict__ duration,   // [B, T] int32
    float* __restrict__ out, long long out_size)
{
    const int b    = blockIdx.x;
    const int tid  = threadIdx.x;
    const int lane = tid & 31;
    const int wid  = tid >> 5;

    __shared__ int wsum[32];

    // clip(|d|, 1, MAX_DUR)
    int dv = duration[b * T_SZ + tid];
    int ad = dv < 0 ? -dv : dv;
    int d  = ad < 1 ? 1 : (ad > MAX_DUR ? MAX_DUR : ad);

    // warp inclusive scan
    int v = d;
    #pragma unroll
    for (int off = 1; off < 32; off <<= 1) {
        int u = __shfl_up_sync(0xFFFFFFFFu, v, off);
        if (lane >= off) v += u;
    }
    if (lane == 31) wsum[wid] = v;
    __syncthreads();

    // warp 0 scans the 32 warp sums
    if (wid == 0) {
        int w = wsum[lane];
        #pragma unroll
        for (int off = 1; off < 32; off <<= 1) {
            int u = __shfl_up_sync(0xFFFFFFFFu, w, off);
            if (lane >= off) w += u;
        }
        wsum[lane] = w;            // inclusive warp-sum scan
    }
    __syncthreads();

    int warp_off = (wid == 0) ? 0 : wsum[wid - 1];
    int end   = v + warp_off;      // inclusive scan value
    int start = end - d;
    int total = wsum[31];

    g_ends[b][tid] = end;
    g_dval[b][tid] = d;

    // Scatter token index to its output span (spans are disjoint)
    int e = end < MAXLEN ? end : MAXLEN;
    for (int p = start; p < e; ++p)
        g_tok[b][p] = tid;

    // Tail fill: invalid positions -> -1
    for (int p = total + tid; p < MAXLEN; p += blockDim.x)
        g_tok[b][p] = -1;

    // mel_len (second output), appended after out[0]; guarded by out_size
    if (tid == 0) {
        long long base = (long long)B_SZ * CH_OUT * MAXLEN;
        if (base + b < out_size)
            out[base + b] = (float)total;
    }
}

// ---------------------------------------------------------------------------
// Kernel 2: streaming expand-gather, 8 channels per block, 2 pos/thread.
// grid = (N_PCHUNK=16, N_YGRP=49, B=32), 256 threads.
// tok loaded ONCE per thread (int2), reused across 8 channels.
// ---------------------------------------------------------------------------
__global__ __launch_bounds__(THREADS) void expand_kernel(
    const float* __restrict__ x,   // [B, C, T]
    float* __restrict__ out)       // [B, CH_OUT, MAXLEN] (+ mel_len tail)
{
    const int b    = blockIdx.z;
    const int yg   = blockIdx.y;
    const int pos0 = (blockIdx.x * THREADS + threadIdx.x) * POS_PER_TH;

    const int2 t2 = *reinterpret_cast<const int2*>(&g_tok[b][pos0]);

    float* const outb = out + (long long)b * CH_OUT * MAXLEN + pos0;

    if (yg < C_SZ / CH_GRP) {
        const int ch0 = yg * CH_GRP;
        const float* const xb = x + ((long long)b * C_SZ + ch0) * T_SZ;
        #pragma unroll
        for (int c = 0; c < CH_GRP; ++c) {
            const float* __restrict__ xrow = xb + c * T_SZ;
            float2 v;
            v.x = (t2.x >= 0) ? __ldg(&xrow[t2.x]) : 0.0f;
            v.y = (t2.y >= 0) ? __ldg(&xrow[t2.y]) : 0.0f;
            *reinterpret_cast<float2*>(outb + (long long)(ch0 + c) * MAXLEN) = v;
        }
    } else {
        // ch 384 = idx_in, ch 385 = length
        float2 iv = {0.f, 0.f};
        float2 lv = {0.f, 0.f};
        if (t2.x >= 0) {
            int dd = g_dval[b][t2.x];
            iv.x = (float)(pos0 + 0 - (g_ends[b][t2.x] - dd)); lv.x = (float)dd;
        }
        if (t2.y >= 0) {
            int dd = g_dval[b][t2.y];
            iv.y = (float)(pos0 + 1 - (g_ends[b][t2.y] - dd)); lv.y = (float)dd;
        }
        float* oi = outb + (long long)C_SZ * MAXLEN;
        *reinterpret_cast<float2*>(oi)          = iv;
        *reinterpret_cast<float2*>(oi + MAXLEN) = lv;
    }
}

// ---------------------------------------------------------------------------
extern "C" void kernel_launch(void* const* d_in, const int* in_sizes, int n_in,
                              void* d_out, int out_size)
{
    const float* x   = (const float*)d_in[0];
    const int*   dur = (const int*)d_in[1];
    float*       out = (float*)d_out;

    prep_kernel<<<B_SZ, 1024>>>(dur, out, (long long)out_size);

    dim3 grid(N_PCHUNK, N_YGRP, B_SZ);
    expand_kernel<<<grid, THREADS>>>(x, out);
}

// round 11
// speedup vs baseline: 1.0255x; 1.0255x over previous
#include <cuda_runtime.h>
#include <stdint.h>

// Problem constants (fixed by setup_inputs)
#define B_SZ     32
#define C_SZ     384
#define T_SZ     1024
#define MAXLEN   8192
#define CH_OUT   (C_SZ + 2)          // 386
#define MAX_DUR  10000

#define THREADS     256
#define POS_PER_TH  4
#define POS_CHUNK   (THREADS * POS_PER_TH)   // 1024
#define N_PCHUNK    (MAXLEN / POS_CHUNK)     // 8
#define CH_GRP      4
#define N_YGRP      (C_SZ / CH_GRP + 1)      // 96 full groups + 1 extras group

// Scratch (allocation-free rule: device globals)
__device__ int g_ends[B_SZ][T_SZ];   // inclusive cumsum of clipped durations
__device__ int g_dval[B_SZ][T_SZ];   // clipped durations
__device__ int g_tok [B_SZ][MAXLEN]; // token per output position, -1 = invalid (monotone tail)

// ---------------------------------------------------------------------------
// Kernel 1: per-batch scan + token-map scatter + tail fill + mel_len.
// One block per batch, 1024 threads. Warp-shfl scan (2 block syncs).
// ---------------------------------------------------------------------------
__global__ __launch_bounds__(1024) void prep_kernel(
    const int* __restrict__ duration,   // [B, T] int32
    float* __restrict__ out, long long out_size)
{
    const int b    = blockIdx.x;
    const int tid  = threadIdx.x;
    const int lane = tid & 31;
    const int wid  = tid >> 5;

    __shared__ int wsum[32];

    // clip(|d|, 1, MAX_DUR)
    int dv = duration[b * T_SZ + tid];
    int ad = dv < 0 ? -dv : dv;
    int d  = ad < 1 ? 1 : (ad > MAX_DUR ? MAX_DUR : ad);

    // warp inclusive scan
    int v = d;
    #pragma unroll
    for (int off = 1; off < 32; off <<= 1) {
        int u = __shfl_up_sync(0xFFFFFFFFu, v, off);
        if (lane >= off) v += u;
    }
    if (lane == 31) wsum[wid] = v;
    __syncthreads();

    // warp 0 scans the 32 warp sums
    if (wid == 0) {
        int w = wsum[lane];
        #pragma unroll
        for (int off = 1; off < 32; off <<= 1) {
            int u = __shfl_up_sync(0xFFFFFFFFu, w, off);
            if (lane >= off) w += u;
        }
        wsum[lane] = w;            // inclusive warp-sum scan
    }
    __syncthreads();

    int warp_off = (wid == 0) ? 0 : wsum[wid - 1];
    int end   = v + warp_off;      // inclusive scan value
    int start = end - d;
    int total = wsum[31];

    g_ends[b][tid] = end;
    g_dval[b][tid] = d;

    // Scatter token index to its output span (spans are disjoint)
    int e = end < MAXLEN ? end : MAXLEN;
    for (int p = start; p < e; ++p)
        g_tok[b][p] = tid;

    // Tail fill: invalid positions -> -1
    for (int p = total + tid; p < MAXLEN; p += blockDim.x)
        g_tok[b][p] = -1;

    // mel_len (second output), appended after out[0]; guarded by out_size
    if (tid == 0) {
        long long base = (long long)B_SZ * CH_OUT * MAXLEN;
        if (base + b < out_size)
            out[base + b] = (float)total;
    }
}

// ---------------------------------------------------------------------------
// Kernel 2: streaming expand-gather, 4 channels per block (R6 config),
// with evict-first streaming stores (single-lever change vs R6).
// grid = (N_PCHUNK=8, N_YGRP=97, B=32), 256 threads, 4 positions/thread.
// ---------------------------------------------------------------------------
__global__ __launch_bounds__(THREADS) void expand_kernel(
    const float* __restrict__ x,   // [B, C, T]
    float* __restrict__ out)       // [B, CH_OUT, MAXLEN] (+ mel_len tail)
{
    const int b    = blockIdx.z;
    const int yg   = blockIdx.y;
    const int pos0 = (blockIdx.x * THREADS + threadIdx.x) * POS_PER_TH;

    const int4 t4 = *reinterpret_cast<const int4*>(&g_tok[b][pos0]);

    float* const outb = out + (long long)b * CH_OUT * MAXLEN + pos0;

    if (yg < C_SZ / CH_GRP) {
        const int ch0 = yg * CH_GRP;
        const float* const xb = x + ((long long)b * C_SZ + ch0) * T_SZ;
        #pragma unroll
        for (int c = 0; c < CH_GRP; ++c) {
            const float* __restrict__ xrow = xb + c * T_SZ;
            float4 v;
            v.x = (t4.x >= 0) ? __ldg(&xrow[t4.x]) : 0.0f;
            v.y = (t4.y >= 0) ? __ldg(&xrow[t4.y]) : 0.0f;
            v.z = (t4.z >= 0) ? __ldg(&xrow[t4.z]) : 0.0f;
            v.w = (t4.w >= 0) ? __ldg(&xrow[t4.w]) : 0.0f;
            __stcs(reinterpret_cast<float4*>(outb + (long long)(ch0 + c) * MAXLEN), v);
        }
    } else {
        // ch 384 = idx_in, ch 385 = length
        float4 iv = {0.f, 0.f, 0.f, 0.f};
        float4 lv = {0.f, 0.f, 0.f, 0.f};
        if (t4.x >= 0) {
            int dd = g_dval[b][t4.x];
            iv.x = (float)(pos0 + 0 - (g_ends[b][t4.x] - dd)); lv.x = (float)dd;
        }
        if (t4.y >= 0) {
            int dd = g_dval[b][t4.y];
            iv.y = (float)(pos0 + 1 - (g_ends[b][t4.y] - dd)); lv.y = (float)dd;
        }
        if (t4.z >= 0) {
            int dd = g_dval[b][t4.z];
            iv.z = (float)(pos0 + 2 - (g_ends[b][t4.z] - dd)); lv.z = (float)dd;
        }
        if (t4.w >= 0) {
            int dd = g_dval[b][t4.w];
            iv.w = (float)(pos0 + 3 - (g_ends[b][t4.w] - dd)); lv.w = (float)dd;
        }
        float* oi = outb + (long long)C_SZ * MAXLEN;
        __stcs(reinterpret_cast<float4*>(oi),          iv);
        __stcs(reinterpret_cast<float4*>(oi + MAXLEN), lv);
    }
}

// ---------------------------------------------------------------------------
extern "C" void kernel_launch(void* const* d_in, const int* in_sizes, int n_in,
                              void* d_out, int out_size)
{
    const float* x   = (const float*)d_in[0];
    const int*   dur = (const int*)d_in[1];
    float*       out = (float*)d_out;

    prep_kernel<<<B_SZ, 1024>>>(dur, out, (long long)out_size);

    dim3 grid(N_PCHUNK, N_YGRP, B_SZ);
    expand_kernel<<<grid, THREADS>>>(x, out);
}

// round 12
// speedup vs baseline: 1.0259x; 1.0004x over previous
#include <cuda_runtime.h>
#include <stdint.h>

// Problem constants (fixed by setup_inputs)
#define B_SZ     32
#define C_SZ     384
#define T_SZ     1024
#define MAXLEN   8192
#define CH_OUT   (C_SZ + 2)          // 386
#define MAX_DUR  10000

#define THREADS     256
#define POS_PER_TH  4
#define POS_CHUNK   (THREADS * POS_PER_TH)   // 1024
#define N_PCHUNK    (MAXLEN / POS_CHUNK)     // 8
#define CH_GRP      4
#define N_YGRP      (C_SZ / CH_GRP + 1)      // 96 full groups + 1 extras group

#define N_FILL      4                        // prep fill blocks per batch
#define FILL_SPAN   (MAXLEN / N_FILL)        // 2048 positions per fill block

// Scratch (allocation-free rule: device globals)
__device__ int g_ends[B_SZ][T_SZ];   // inclusive cumsum of clipped durations
__device__ int g_dval[B_SZ][T_SZ];   // clipped durations
__device__ int g_tok [B_SZ][MAXLEN]; // token per output position, -1 = invalid (monotone tail)

// ---------------------------------------------------------------------------
// Kernel 1: scan + binary-search tok fill. grid = (N_FILL=4, B_SZ=32),
// 1024 threads. Every block redoes the cheap per-batch scan (keeps blocks
// independent); each fills a 2048-position slice of g_tok with coalesced
// int2 stores via branchless smem binary search. Block x==0 also writes
// g_ends / g_dval / mel_len.
// ---------------------------------------------------------------------------
__global__ __launch_bounds__(1024) void prep_kernel(
    const int* __restrict__ duration,   // [B, T] int32
    float* __restrict__ out, long long out_size)
{
    const int b    = blockIdx.y;
    const int slice= blockIdx.x;
    const int tid  = threadIdx.x;
    const int lane = tid & 31;
    const int wid  = tid >> 5;

    __shared__ int s_ends[T_SZ];
    __shared__ int wsum[32];

    // clip(|d|, 1, MAX_DUR)
    int dv = duration[b * T_SZ + tid];
    int ad = dv < 0 ? -dv : dv;
    int d  = ad < 1 ? 1 : (ad > MAX_DUR ? MAX_DUR : ad);

    // warp inclusive scan
    int v = d;
    #pragma unroll
    for (int off = 1; off < 32; off <<= 1) {
        int u = __shfl_up_sync(0xFFFFFFFFu, v, off);
        if (lane >= off) v += u;
    }
    if (lane == 31) wsum[wid] = v;
    __syncthreads();

    // warp 0 scans the 32 warp sums
    if (wid == 0) {
        int w = wsum[lane];
        #pragma unroll
        for (int off = 1; off < 32; off <<= 1) {
            int u = __shfl_up_sync(0xFFFFFFFFu, w, off);
            if (lane >= off) w += u;
        }
        wsum[lane] = w;            // inclusive warp-sum scan
    }
    __syncthreads();

    int warp_off = (wid == 0) ? 0 : wsum[wid - 1];
    int end   = v + warp_off;      // inclusive scan value
    int total = wsum[31];

    s_ends[tid] = end;

    if (slice == 0) {
        g_ends[b][tid] = end;
        g_dval[b][tid] = d;
        // mel_len (second output), appended after out[0]; guarded by out_size
        if (tid == 0) {
            long long base = (long long)B_SZ * CH_OUT * MAXLEN;
            if (base + b < out_size)
                out[base + b] = (float)total;
        }
    }
    __syncthreads();

    // Fill this block's 2048-position slice: 2 positions/thread, int2 stores.
    // tok(p) = searchsorted_right(ends, p) via branchless lower bound on
    // "ends[i] > p" (== count of ends <= p); -1 for p >= total.
    const int p0 = slice * FILL_SPAN + tid * 2;
    int2 tw;
    {
        int p = p0;
        int idx = 0;
        #pragma unroll
        for (int step = T_SZ / 2; step > 0; step >>= 1)
            if (s_ends[idx + step - 1] <= p) idx += step;
        tw.x = (p < total) ? (idx < T_SZ - 1 ? idx : T_SZ - 1) : -1;
    }
    {
        int p = p0 + 1;
        int idx = 0;
        #pragma unroll
        for (int step = T_SZ / 2; step > 0; step >>= 1)
            if (s_ends[idx + step - 1] <= p) idx += step;
        tw.y = (p < total) ? (idx < T_SZ - 1 ? idx : T_SZ - 1) : -1;
    }
    *reinterpret_cast<int2*>(&g_tok[b][p0]) = tw;
}

// ---------------------------------------------------------------------------
// Kernel 2: streaming expand-gather (unchanged from R11 committed version).
// grid = (N_PCHUNK=8, N_YGRP=97, B=32), 256 threads, 4 positions/thread,
// 4 channels per block, evict-first stores.
// ---------------------------------------------------------------------------
__global__ __launch_bounds__(THREADS) void expand_kernel(
    const float* __restrict__ x,   // [B, C, T]
    float* __restrict__ out)       // [B, CH_OUT, MAXLEN] (+ mel_len tail)
{
    const int b    = blockIdx.z;
    const int yg   = blockIdx.y;
    const int pos0 = (blockIdx.x * THREADS + threadIdx.x) * POS_PER_TH;

    const int4 t4 = *reinterpret_cast<const int4*>(&g_tok[b][pos0]);

    float* const outb = out + (long long)b * CH_OUT * MAXLEN + pos0;

    if (yg < C_SZ / CH_GRP) {
        const int ch0 = yg * CH_GRP;
        const float* const xb = x + ((long long)b * C_SZ + ch0) * T_SZ;
        #pragma unroll
        for (int c = 0; c < CH_GRP; ++c) {
            const float* __restrict__ xrow = xb + c * T_SZ;
            float4 v;
            v.x = (t4.x >= 0) ? __ldg(&xrow[t4.x]) : 0.0f;
            v.y = (t4.y >= 0) ? __ldg(&xrow[t4.y]) : 0.0f;
            v.z = (t4.z >= 0) ? __ldg(&xrow[t4.z]) : 0.0f;
            v.w = (t4.w >= 0) ? __ldg(&xrow[t4.w]) : 0.0f;
            __stcs(reinterpret_cast<float4*>(outb + (long long)(ch0 + c) * MAXLEN), v);
        }
    } else {
        // ch 384 = idx_in, ch 385 = length
        float4 iv = {0.f, 0.f, 0.f, 0.f};
        float4 lv = {0.f, 0.f, 0.f, 0.f};
        if (t4.x >= 0) {
            int dd = g_dval[b][t4.x];
            iv.x = (float)(pos0 + 0 - (g_ends[b][t4.x] - dd)); lv.x = (float)dd;
        }
        if (t4.y >= 0) {
            int dd = g_dval[b][t4.y];
            iv.y = (float)(pos0 + 1 - (g_ends[b][t4.y] - dd)); lv.y = (float)dd;
        }
        if (t4.z >= 0) {
            int dd = g_dval[b][t4.z];
            iv.z = (float)(pos0 + 2 - (g_ends[b][t4.z] - dd)); lv.z = (float)dd;
        }
        if (t4.w >= 0) {
            int dd = g_dval[b][t4.w];
            iv.w = (float)(pos0 + 3 - (g_ends[b][t4.w] - dd)); lv.w = (float)dd;
        }
        float* oi = outb + (long long)C_SZ * MAXLEN;
        __stcs(reinterpret_cast<float4*>(oi),          iv);
        __stcs(reinterpret_cast<float4*>(oi + MAXLEN), lv);
    }
}

// ---------------------------------------------------------------------------
extern "C" void kernel_launch(void* const* d_in, const int* in_sizes, int n_in,
                              void* d_out, int out_size)
{
    const float* x   = (const float*)d_in[0];
    const int*   dur = (const int*)d_in[1];
    float*       out = (float*)d_out;

    dim3 pgrid(N_FILL, B_SZ);
    prep_kernel<<<pgrid, 1024>>>(dur, out, (long long)out_size);

    dim3 grid(N_PCHUNK, N_YGRP, B_SZ);
    expand_kernel<<<grid, THREADS>>>(x, out);
}